// round 7
// baseline (speedup 1.0000x reference)
#include <cuda_runtime.h>
#include <cuda_fp16.h>
#include <cstdint>

// ============================================================
// FFTEmbedding as implicit-im2col GEMM (sm_100 legacy-HMMA path)
//   out = A(131072x256 Toeplitz windows) @ WeffT(512x256)^T + bias
// R7 (base R4): fully decoupled warps — A Toeplitz values loaded
//   per-warp straight from global (L1/L2-hot), NO shared segment,
//   NO per-iteration __syncthreads. Boundary tiles via SAFE branch.
// ============================================================

#define B_SZ   16
#define T_SZ   8192
#define W_SZ   256
#define EMB    512
#define NFEAT  258

#define BM 128
#define BN 128
#define MTILES 1024           // (B*T)/BM
#define GRID   296            // 2 CTAs per SM
#define CTAS_PER_N 74         // GRID / 4 N-tiles
#define THREADS 256

#define PB 264                // B smem pitch in halfs (256 + 8 pad)
#define SMEM_B_BYTES (128 * PB * 2)            // 67584
#define SMEM_TOTAL   SMEM_B_BYTES

// fp16 Weff^T, [EMB][W_SZ]
__device__ __half g_weffT[EMB * W_SZ];

__device__ __forceinline__ uint32_t smem_to_u32(const void* p) {
    uint32_t a;
    asm("{ .reg .u64 t; cvta.to.shared.u64 t, %1; cvt.u32.u64 %0, t; }" : "=r"(a) : "l"(p));
    return a;
}

template<bool SAFE>
__device__ __forceinline__ uint32_t ldcvt_x(const float* __restrict__ xb, int gx) {
    float f0, f1;
    if (SAFE) {
        f0 = (gx >= 0)     ? __ldg(xb + gx)     : 0.0f;
        f1 = (gx + 1 >= 0) ? __ldg(xb + gx + 1) : 0.0f;
    } else {
        f0 = __ldg(xb + gx);
        f1 = __ldg(xb + gx + 1);
    }
    __half2 h = __floats2half2_rn(f0, f1);
    return *reinterpret_cast<uint32_t*>(&h);
}

__device__ __forceinline__ void mma16816(float* c, uint32_t a0, uint32_t a1,
                                         uint32_t a2, uint32_t a3,
                                         uint32_t b0, uint32_t b1) {
    asm volatile(
        "mma.sync.aligned.m16n8k16.row.col.f32.f16.f16.f32 "
        "{%0,%1,%2,%3}, {%4,%5,%6,%7}, {%8,%9}, {%0,%1,%2,%3};"
        : "+f"(c[0]), "+f"(c[1]), "+f"(c[2]), "+f"(c[3])
        : "r"(a0), "r"(a1), "r"(a2), "r"(a3), "r"(b0), "r"(b1));
}

__device__ __forceinline__ void ldmatrix_x4(uint32_t& r0, uint32_t& r1,
                                            uint32_t& r2, uint32_t& r3, uint32_t addr) {
    asm volatile("ldmatrix.sync.aligned.m8n8.x4.shared.b16 {%0,%1,%2,%3}, [%4];"
                 : "=r"(r0), "=r"(r1), "=r"(r2), "=r"(r3) : "r"(addr));
}

// Column permutation within each warp's 16-col slice (enables STG.128).
__device__ __host__ __forceinline__ int permcol(int s) {
    return (s < 8) ? ((s & 1) ? 2 * s - 1 : 2 * s)
                   : ((s & 1) ? 2 * s - 15 : 2 * s - 14);
}

// ============================================================
// Kernel 1: Weff^T precompute (angle recurrence)
// ============================================================
__global__ void weff_kernel(const float* __restrict__ weight) {
    __shared__ float w1[129], w2[129];
    const int e = blockIdx.x;
    for (int f = threadIdx.x; f < NFEAT; f += 256) {
        float v = weight[e * NFEAT + f];
        if (f < 129) w1[f] = v; else w2[f - 129] = v;
    }
    __syncthreads();
    const int n = threadIdx.x;                // k position 0..255
    float s1, c1;
    sincospif((float)n / 128.0f, &s1, &c1);   // step angle 2*pi*n/256
    float acc = w1[0];
    float c = c1, s = s1;
    #pragma unroll 4
    for (int kk = 1; kk <= 128; kk++) {
        acc = fmaf(c, w1[kk], acc);
        acc = fmaf(-s, w2[kk], acc);
        float cn = fmaf(c, c1, -s * s1);
        float sn = fmaf(s, c1,  c * s1);
        c = cn; s = sn;
    }
    g_weffT[e * W_SZ + n] = __float2half_rn(acc);
}

// ============================================================
// Per-M-tile body: rolling Toeplitz window from GLOBAL, 16 k-steps,
// permuted STG.128 epilogue. SAFE=true only for t0 < 256 tiles.
// ============================================================
template<bool SAFE>
__device__ __forceinline__ void tile_body(
    const float* __restrict__ xb, int g0, uint32_t baddr0,
    float* __restrict__ out, size_t rowb, int colb, float4 bias4)
{
    float acc[8][2][4];
    #pragma unroll
    for (int m = 0; m < 8; m++)
        #pragma unroll
        for (int n = 0; n < 2; n++)
            #pragma unroll
            for (int c = 0; c < 4; c++) acc[m][n][c] = 0.0f;

    // Toeplitz A: av[j] = half2(x[g0 + 8j], x[g0 + 8j + 1])
    uint32_t av[17];
    #pragma unroll
    for (int j = 0; j < 17; j++) av[j] = ldcvt_x<SAFE>(xb, g0 + 8 * j);

    #pragma unroll
    for (int ks = 0; ks < 16; ks++) {
        uint32_t b0, b1, b2, b3;
        ldmatrix_x4(b0, b1, b2, b3, baddr0 + (uint32_t)(ks * 32));
        #pragma unroll
        for (int m = 0; m < 8; m++) {
            mma16816(acc[m][0], av[2*m], av[2*m+1], av[2*m+1], av[2*m+2], b0, b1);
            mma16816(acc[m][1], av[2*m], av[2*m+1], av[2*m+1], av[2*m+2], b2, b3);
        }
        if (ks < 15) {
            #pragma unroll
            for (int j = 0; j < 15; j++) av[j] = av[j + 2];
            av[15] = ldcvt_x<SAFE>(xb, g0 + 8 * (2 * ks + 17));
            av[16] = ldcvt_x<SAFE>(xb, g0 + 8 * (2 * ks + 18));
        }
    }

    // ---- epilogue: bias + STG.128 (permuted cols contiguous) ----
    #pragma unroll
    for (int m = 0; m < 8; m++) {
        float* o0 = out + (rowb + 16 * m) * EMB + colb;
        float* o1 = o0 + 8 * EMB;
        float4 v0 = make_float4(acc[m][0][0] + bias4.x, acc[m][0][1] + bias4.y,
                                acc[m][1][0] + bias4.z, acc[m][1][1] + bias4.w);
        float4 v1 = make_float4(acc[m][0][2] + bias4.x, acc[m][0][3] + bias4.y,
                                acc[m][1][2] + bias4.z, acc[m][1][3] + bias4.w);
        *reinterpret_cast<float4*>(o0) = v0;
        *reinterpret_cast<float4*>(o1) = v1;
    }
}

// ============================================================
// Kernel 2: persistent GEMM, grid=296 (2 CTAs/SM), 256 threads
// warp tile: 128m x 16n; warps fully decoupled (no loop barriers)
// ============================================================
__global__ void __launch_bounds__(THREADS, 2) fft_gemm_kernel(
    const float* __restrict__ x,
    const float* __restrict__ bias,
    float* __restrict__ out)
{
    extern __shared__ char smem[];
    __half* Bs = (__half*)smem;

    const int tid  = threadIdx.x;
    const int wid  = tid >> 5;
    const int lane = tid & 31;
    const int q    = lane & 3;
    const int r4   = lane >> 2;
    const int ntile = (int)(blockIdx.x & 3);
    const int e0    = ntile * BN;

    // ---- load B tile (WeffT rows e0..e0+127), permuted within slices ----
    for (int u = tid; u < 4096; u += THREADS) {
        int r  = u >> 5;
        int ch = u & 31;
        int esrc = e0 + (r & ~15) + permcol(r & 15);
        uint4 v = *reinterpret_cast<const uint4*>(&g_weffT[esrc * W_SZ + ch * 8]);
        *reinterpret_cast<uint4*>(Bs + r * PB + ch * 8) = v;
    }

    // ---- per-thread bias: 4 contiguous cols ----
    const int colb = e0 + wid * 16 + 4 * q;
    const float4 bias4 = *reinterpret_cast<const float4*>(bias + colb);

    // ---- ldmatrix base address for this warp's 16-row B slice ----
    const uint32_t sbB = smem_to_u32(Bs);
    const int brow = wid * 16 + (lane & 7) + ((lane & 16) ? 8 : 0);
    const int bkof = (lane & 8) ? 8 : 0;
    const uint32_t baddr0 = sbB + (uint32_t)(brow * PB + bkof) * 2u;

    const int base0 = r4 + 2 * q;          // 0..13
    __syncthreads();                       // B tile ready (only barrier)

    const int mt0 = (int)(blockIdx.x >> 2);
    for (int mt = mt0; mt < MTILES; mt += CTAS_PER_N) {
        const int bidx = mt >> 6;
        const int t0   = (mt & 63) * BM;
        const float* xb = x + bidx * T_SZ;
        const int g0 = t0 - (W_SZ - 1) + base0;
        const size_t rowb = (size_t)mt * BM + (size_t)r4;

        if (t0 >= W_SZ) {                  // window fully inside x
            tile_body<false>(xb, g0, baddr0, out, rowb, colb, bias4);
        } else {                           // 2 of 64 tiles touch zero-pad
            tile_body<true>(xb, g0, baddr0, out, rowb, colb, bias4);
        }
    }
}

// ============================================================
extern "C" void kernel_launch(void* const* d_in, const int* in_sizes, int n_in,
                              void* d_out, int out_size) {
    const float* x  = nullptr;
    const float* wt = nullptr;
    const float* bs = nullptr;
    for (int i = 0; i < n_in; i++) {
        if (in_sizes[i] == B_SZ * T_SZ)        x  = (const float*)d_in[i];
        else if (in_sizes[i] == EMB * NFEAT)   wt = (const float*)d_in[i];
        else if (in_sizes[i] == EMB)           bs = (const float*)d_in[i];
    }

    weff_kernel<<<EMB, 256>>>(wt);

    cudaFuncSetAttribute(fft_gemm_kernel,
                         cudaFuncAttributeMaxDynamicSharedMemorySize, SMEM_TOTAL);
    fft_gemm_kernel<<<GRID, THREADS, SMEM_TOTAL>>>(x, bs, (float*)d_out);
}

// round 8
// speedup vs baseline: 1.1668x; 1.1668x over previous
#include <cuda_runtime.h>
#include <cuda_fp16.h>
#include <cstdint>

// ============================================================
// FFTEmbedding as implicit-im2col GEMM (sm_100 legacy-HMMA path)
//   out = A(131072x256 Toeplitz windows) @ WeffT(512x256)^T + bias
// R8 = R4 + split-phase mbarrier: arrive after seg-store, wait
//   after epilogue. Epilogue leaves the inter-warp critical path;
//   warps/CTAs desync so the tensor pipe stays fed.
// ============================================================

#define B_SZ   16
#define T_SZ   8192
#define W_SZ   256
#define EMB    512
#define NFEAT  258

#define BM 128
#define BN 128
#define MTILES 1024           // (B*T)/BM
#define GRID   296            // 2 CTAs per SM
#define CTAS_PER_N 74         // GRID / 4 N-tiles
#define THREADS 256

#define PB 264                // B smem pitch in halfs (256 + 8 pad)
#define SMEM_B_BYTES (128 * PB * 2)            // 67584
#define OFF_MBAR  SMEM_B_BYTES                 // 8 bytes + 8 pad
#define OFF_SEG   (SMEM_B_BYTES + 16)
#define SMEM_TOTAL (OFF_SEG + 2 * 384 * 4)

// fp16 Weff^T, [EMB][W_SZ]
__device__ __half g_weffT[EMB * W_SZ];

__device__ __forceinline__ uint32_t smem_to_u32(const void* p) {
    uint32_t a;
    asm("{ .reg .u64 t; cvta.to.shared.u64 t, %1; cvt.u32.u64 %0, t; }" : "=r"(a) : "l"(p));
    return a;
}

__device__ __forceinline__ uint32_t ldcvt(const float* s) {
    __half2 h = __floats2half2_rn(s[0], s[1]);
    return *reinterpret_cast<uint32_t*>(&h);
}

__device__ __forceinline__ void mma16816(float* c, uint32_t a0, uint32_t a1,
                                         uint32_t a2, uint32_t a3,
                                         uint32_t b0, uint32_t b1) {
    asm volatile(
        "mma.sync.aligned.m16n8k16.row.col.f32.f16.f16.f32 "
        "{%0,%1,%2,%3}, {%4,%5,%6,%7}, {%8,%9}, {%0,%1,%2,%3};"
        : "+f"(c[0]), "+f"(c[1]), "+f"(c[2]), "+f"(c[3])
        : "r"(a0), "r"(a1), "r"(a2), "r"(a3), "r"(b0), "r"(b1));
}

__device__ __forceinline__ void ldmatrix_x4(uint32_t& r0, uint32_t& r1,
                                            uint32_t& r2, uint32_t& r3, uint32_t addr) {
    asm volatile("ldmatrix.sync.aligned.m8n8.x4.shared.b16 {%0,%1,%2,%3}, [%4];"
                 : "=r"(r0), "=r"(r1), "=r"(r2), "=r"(r3) : "r"(addr));
}

#define MBARRIER_INIT(addr, count) \
    asm volatile("mbarrier.init.shared.b64 [%0], %1;" \
        :: "r"((uint32_t)(addr)), "r"((uint32_t)(count)) : "memory")

#define MBARRIER_ARRIVE(addr) \
    asm volatile("mbarrier.arrive.release.cta.shared.b64 _, [%0];" \
        :: "r"((uint32_t)(addr)) : "memory")

#define MBARRIER_WAIT_PARITY(mbar_smem_addr, phase_parity) do { \
    uint32_t _mbar = (uint32_t)(mbar_smem_addr); \
    uint32_t _parity = (uint32_t)(phase_parity); \
    uint32_t _done; \
    asm volatile( \
        "{\n\t.reg .pred p;\n\t" \
        "mbarrier.try_wait.parity.acquire.cta.shared::cta.b64 p, [%1], %2;\n\t" \
        "selp.b32 %0, 1, 0, p;\n\t}" \
        : "=r"(_done) : "r"(_mbar), "r"(_parity) : "memory"); \
    if (!_done) { \
        asm volatile( \
            "{\n\t.reg .pred P1;\n\t" \
            "WAIT_LOOP_%=:\n\t" \
            "mbarrier.try_wait.parity.acquire.cta.shared::cta.b64 P1, [%0], %1, 0x989680;\n\t" \
            "@P1 bra.uni WAIT_DONE_%=;\n\t" \
            "bra.uni WAIT_LOOP_%=;\n\t" \
            "WAIT_DONE_%=:\n\t}" \
            :: "r"(_mbar), "r"(_parity) : "memory"); \
    } \
} while(0)

// Column permutation within each warp's 16-col slice (enables STG.128).
__device__ __host__ __forceinline__ int permcol(int s) {
    return (s < 8) ? ((s & 1) ? 2 * s - 1 : 2 * s)
                   : ((s & 1) ? 2 * s - 15 : 2 * s - 14);
}

// ============================================================
// Kernel 1: Weff^T precompute (angle recurrence)
// ============================================================
__global__ void weff_kernel(const float* __restrict__ weight) {
    __shared__ float w1[129], w2[129];
    const int e = blockIdx.x;
    for (int f = threadIdx.x; f < NFEAT; f += 256) {
        float v = weight[e * NFEAT + f];
        if (f < 129) w1[f] = v; else w2[f - 129] = v;
    }
    __syncthreads();
    const int n = threadIdx.x;                // k position 0..255
    float s1, c1;
    sincospif((float)n / 128.0f, &s1, &c1);   // step angle 2*pi*n/256
    float acc = w1[0];
    float c = c1, s = s1;
    #pragma unroll 4
    for (int kk = 1; kk <= 128; kk++) {
        acc = fmaf(c, w1[kk], acc);
        acc = fmaf(-s, w2[kk], acc);
        float cn = fmaf(c, c1, -s * s1);
        float sn = fmaf(s, c1,  c * s1);
        c = cn; s = sn;
    }
    g_weffT[e * W_SZ + n] = __float2half_rn(acc);
}

// ============================================================
// Kernel 2: persistent GEMM, grid=296 (2 CTAs/SM), 256 threads
// warp tile: 128m x 16n; split-phase mbarrier per iteration
// ============================================================
__global__ void __launch_bounds__(THREADS, 2) fft_gemm_kernel(
    const float* __restrict__ x,
    const float* __restrict__ bias,
    float* __restrict__ out)
{
    extern __shared__ char smem[];
    __half* Bs = (__half*)smem;
    float (*seg)[384] = (float(*)[384])(smem + OFF_SEG);
    const uint32_t sb = smem_to_u32(smem);
    const uint32_t mbar = sb + OFF_MBAR;

    const int tid  = threadIdx.x;
    const int wid  = tid >> 5;
    const int lane = tid & 31;
    const int q    = lane & 3;
    const int r4   = lane >> 2;
    const int ntile = (int)(blockIdx.x & 3);
    const int e0    = ntile * BN;

    if (tid == 0) MBARRIER_INIT(mbar, THREADS);

    // ---- load B tile (WeffT rows e0..e0+127), permuted within slices ----
    for (int u = tid; u < 4096; u += THREADS) {
        int r  = u >> 5;
        int ch = u & 31;
        int esrc = e0 + (r & ~15) + permcol(r & 15);
        uint4 v = *reinterpret_cast<const uint4*>(&g_weffT[esrc * W_SZ + ch * 8]);
        *reinterpret_cast<uint4*>(Bs + r * PB + ch * 8) = v;
    }

    // ---- per-thread bias: 4 contiguous cols ----
    const int colb = e0 + wid * 16 + 4 * q;
    const float4 bias4 = *reinterpret_cast<const float4*>(bias + colb);

    // ---- ldmatrix base address for this warp's 16-row B slice ----
    const uint32_t sbB = smem_to_u32(Bs);
    const int brow = wid * 16 + (lane & 7) + ((lane & 16) ? 8 : 0);
    const int bkof = (lane & 8) ? 8 : 0;
    const uint32_t baddr0 = sbB + (uint32_t)(brow * PB + bkof) * 2u;

    // ---- initial segment load for first M-tile ----
    const int mt0 = (int)(blockIdx.x >> 2);
    {
        int bidx = mt0 >> 6, t0 = (mt0 & 63) * BM;
        int gx0 = t0 + tid - (W_SZ - 1);
        seg[0][tid] = (gx0 >= 0) ? x[bidx * T_SZ + gx0] : 0.0f;
        if (tid < 128) {
            int j = 256 + tid;
            int gx1 = t0 + j - (W_SZ - 1);
            seg[0][j] = (j < 383 && gx1 >= 0) ? x[bidx * T_SZ + gx1] : 0.0f;
        }
    }
    __syncthreads();   // B tile + seg[0] + mbarrier init visible

    int pb = 0, ph = 0;
    for (int mt = mt0; mt < MTILES; mt += CTAS_PER_N, pb ^= 1) {
        // ---- prefetch next segment into registers ----
        const int mtn = mt + CTAS_PER_N;
        float p0 = 0.0f, p1 = 0.0f;
        if (mtn < MTILES) {
            int bidx = mtn >> 6, t0 = (mtn & 63) * BM;
            int gx0 = t0 + tid - (W_SZ - 1);
            if (gx0 >= 0) p0 = x[bidx * T_SZ + gx0];
            if (tid < 128) {
                int j = 256 + tid;
                int gx1 = t0 + j - (W_SZ - 1);
                if (j < 383 && gx1 >= 0) p1 = x[bidx * T_SZ + gx1];
            }
        }

        // ---- MMA mainloop: K=256 (16 k-steps), 8 m-tiles, 2 n-tiles ----
        float acc[8][2][4];
        #pragma unroll
        for (int m = 0; m < 8; m++)
            #pragma unroll
            for (int n = 0; n < 2; n++)
                #pragma unroll
                for (int c = 0; c < 4; c++) acc[m][n][c] = 0.0f;

        const float* sg = seg[pb];
        const int base0 = r4 + 2 * q;

        // Toeplitz A: av[j] = half2(seg[base0 + 16*ks + 8j .. +1])
        uint32_t av[17];
        #pragma unroll
        for (int j = 0; j < 17; j++) av[j] = ldcvt(sg + base0 + 8 * j);

        #pragma unroll
        for (int ks = 0; ks < 16; ks++) {
            uint32_t b0, b1, b2, b3;
            ldmatrix_x4(b0, b1, b2, b3, baddr0 + (uint32_t)(ks * 32));
            #pragma unroll
            for (int m = 0; m < 8; m++) {
                mma16816(acc[m][0], av[2*m], av[2*m+1], av[2*m+1], av[2*m+2], b0, b1);
                mma16816(acc[m][1], av[2*m], av[2*m+1], av[2*m+1], av[2*m+2], b2, b3);
            }
            if (ks < 15) {
                #pragma unroll
                for (int j = 0; j < 15; j++) av[j] = av[j + 2];
                av[15] = ldcvt(sg + base0 + 16 * (ks + 1) + 120);
                av[16] = ldcvt(sg + base0 + 16 * (ks + 1) + 128);
            }
        }

        // ---- store prefetched segment, then ARRIVE (mainloop reads done) ----
        if (mtn < MTILES) {
            seg[pb ^ 1][tid] = p0;
            if (tid < 128) seg[pb ^ 1][256 + tid] = p1;
            MBARRIER_ARRIVE(mbar);
        }

        // ---- epilogue (outside critical path): bias + STG.128 ----
        const size_t rowb = (size_t)mt * BM + (size_t)r4;
        #pragma unroll
        for (int m = 0; m < 8; m++) {
            float* o0 = out + (rowb + 16 * m) * EMB + colb;
            float* o1 = o0 + 8 * EMB;
            float4 v0 = make_float4(acc[m][0][0] + bias4.x, acc[m][0][1] + bias4.y,
                                    acc[m][1][0] + bias4.z, acc[m][1][1] + bias4.w);
            float4 v1 = make_float4(acc[m][0][2] + bias4.x, acc[m][0][3] + bias4.y,
                                    acc[m][1][2] + bias4.z, acc[m][1][3] + bias4.w);
            *reinterpret_cast<float4*>(o0) = v0;
            *reinterpret_cast<float4*>(o1) = v1;
        }

        // ---- wait for all warps' arrivals before next mainloop ----
        if (mtn < MTILES) {
            MBARRIER_WAIT_PARITY(mbar, ph);
            ph ^= 1;
        }
    }
}

// ============================================================
extern "C" void kernel_launch(void* const* d_in, const int* in_sizes, int n_in,
                              void* d_out, int out_size) {
    const float* x  = nullptr;
    const float* wt = nullptr;
    const float* bs = nullptr;
    for (int i = 0; i < n_in; i++) {
        if (in_sizes[i] == B_SZ * T_SZ)        x  = (const float*)d_in[i];
        else if (in_sizes[i] == EMB * NFEAT)   wt = (const float*)d_in[i];
        else if (in_sizes[i] == EMB)           bs = (const float*)d_in[i];
    }

    weff_kernel<<<EMB, 256>>>(wt);

    cudaFuncSetAttribute(fft_gemm_kernel,
                         cudaFuncAttributeMaxDynamicSharedMemorySize, SMEM_TOTAL);
    fft_gemm_kernel<<<GRID, THREADS, SMEM_TOTAL>>>(x, bs, (float*)d_out);
}

// round 11
// speedup vs baseline: 1.2129x; 1.0395x over previous
#include <cuda_runtime.h>
#include <cuda_fp16.h>
#include <cstdint>

// ============================================================
// FFTEmbedding as implicit-im2col GEMM (sm_100 legacy-HMMA path)
//   out = A(131072x256 Toeplitz windows) @ WeffT(512x256)^T + bias
// R11 = R10 resubmitted unchanged (R10 audit: memory-safe; the
//   container failure was infra-side). 4 CTAs/SM x 128 threads,
//   CTA tile 128m x 64n, grid 592; split-phase mbarrier per iter.
// ============================================================

#define B_SZ   16
#define T_SZ   8192
#define W_SZ   256
#define EMB    512
#define NFEAT  258

#define BM 128
#define BN 64                 // CTA n-tile
#define MTILES 1024           // (B*T)/BM
#define NGROUPS 8             // EMB/BN
#define GRID   592            // 4 CTAs per SM
#define CTAS_PER_N 74         // GRID / NGROUPS
#define THREADS 128

#define PB 264                // B smem pitch in halfs (256 + 8 pad)
#define SMEM_B_BYTES (64 * PB * 2)             // 33792
#define OFF_MBAR  SMEM_B_BYTES                 // 8 bytes + 8 pad
#define OFF_SEG   (SMEM_B_BYTES + 16)
#define SMEM_TOTAL (OFF_SEG + 2 * 384 * 4)

// fp16 Weff^T, [EMB][W_SZ]
__device__ __half g_weffT[EMB * W_SZ];

__device__ __forceinline__ uint32_t smem_to_u32(const void* p) {
    uint32_t a;
    asm("{ .reg .u64 t; cvta.to.shared.u64 t, %1; cvt.u32.u64 %0, t; }" : "=r"(a) : "l"(p));
    return a;
}

__device__ __forceinline__ uint32_t ldcvt(const float* s) {
    __half2 h = __floats2half2_rn(s[0], s[1]);
    return *reinterpret_cast<uint32_t*>(&h);
}

__device__ __forceinline__ void mma16816(float* c, uint32_t a0, uint32_t a1,
                                         uint32_t a2, uint32_t a3,
                                         uint32_t b0, uint32_t b1) {
    asm volatile(
        "mma.sync.aligned.m16n8k16.row.col.f32.f16.f16.f32 "
        "{%0,%1,%2,%3}, {%4,%5,%6,%7}, {%8,%9}, {%0,%1,%2,%3};"
        : "+f"(c[0]), "+f"(c[1]), "+f"(c[2]), "+f"(c[3])
        : "r"(a0), "r"(a1), "r"(a2), "r"(a3), "r"(b0), "r"(b1));
}

__device__ __forceinline__ void ldmatrix_x4(uint32_t& r0, uint32_t& r1,
                                            uint32_t& r2, uint32_t& r3, uint32_t addr) {
    asm volatile("ldmatrix.sync.aligned.m8n8.x4.shared.b16 {%0,%1,%2,%3}, [%4];"
                 : "=r"(r0), "=r"(r1), "=r"(r2), "=r"(r3) : "r"(addr));
}

#define MBARRIER_INIT(addr, count) \
    asm volatile("mbarrier.init.shared.b64 [%0], %1;" \
        :: "r"((uint32_t)(addr)), "r"((uint32_t)(count)) : "memory")

#define MBARRIER_ARRIVE(addr) \
    asm volatile("mbarrier.arrive.release.cta.shared.b64 _, [%0];" \
        :: "r"((uint32_t)(addr)) : "memory")

#define MBARRIER_WAIT_PARITY(mbar_smem_addr, phase_parity) do { \
    uint32_t _mbar = (uint32_t)(mbar_smem_addr); \
    uint32_t _parity = (uint32_t)(phase_parity); \
    uint32_t _done; \
    asm volatile( \
        "{\n\t.reg .pred p;\n\t" \
        "mbarrier.try_wait.parity.acquire.cta.shared::cta.b64 p, [%1], %2;\n\t" \
        "selp.b32 %0, 1, 0, p;\n\t}" \
        : "=r"(_done) : "r"(_mbar), "r"(_parity) : "memory"); \
    if (!_done) { \
        asm volatile( \
            "{\n\t.reg .pred P1;\n\t" \
            "WAIT_LOOP_%=:\n\t" \
            "mbarrier.try_wait.parity.acquire.cta.shared::cta.b64 P1, [%0], %1, 0x989680;\n\t" \
            "@P1 bra.uni WAIT_DONE_%=;\n\t" \
            "bra.uni WAIT_LOOP_%=;\n\t" \
            "WAIT_DONE_%=:\n\t}" \
            :: "r"(_mbar), "r"(_parity) : "memory"); \
    } \
} while(0)

// Column permutation within each warp's 16-col slice (enables STG.128).
__device__ __host__ __forceinline__ int permcol(int s) {
    return (s < 8) ? ((s & 1) ? 2 * s - 1 : 2 * s)
                   : ((s & 1) ? 2 * s - 15 : 2 * s - 14);
}

// ============================================================
// Kernel 1: Weff^T precompute (angle recurrence)
// ============================================================
__global__ void weff_kernel(const float* __restrict__ weight) {
    __shared__ float w1[129], w2[129];
    const int e = blockIdx.x;
    for (int f = threadIdx.x; f < NFEAT; f += 256) {
        float v = weight[e * NFEAT + f];
        if (f < 129) w1[f] = v; else w2[f - 129] = v;
    }
    __syncthreads();
    const int n = threadIdx.x;                // k position 0..255
    float s1, c1;
    sincospif((float)n / 128.0f, &s1, &c1);   // step angle 2*pi*n/256
    float acc = w1[0];
    float c = c1, s = s1;
    #pragma unroll 4
    for (int kk = 1; kk <= 128; kk++) {
        acc = fmaf(c, w1[kk], acc);
        acc = fmaf(-s, w2[kk], acc);
        float cn = fmaf(c, c1, -s * s1);
        float sn = fmaf(s, c1,  c * s1);
        c = cn; s = sn;
    }
    g_weffT[e * W_SZ + n] = __float2half_rn(acc);
}

// ============================================================
// Kernel 2: persistent GEMM, grid=592 (4 CTAs/SM), 128 threads
// warp tile: 128m x 16n; split-phase mbarrier per iteration
// ============================================================
__global__ void __launch_bounds__(THREADS, 4) fft_gemm_kernel(
    const float* __restrict__ x,
    const float* __restrict__ bias,
    float* __restrict__ out)
{
    extern __shared__ char smem[];
    __half* Bs = (__half*)smem;
    float (*seg)[384] = (float(*)[384])(smem + OFF_SEG);
    const uint32_t sb = smem_to_u32(smem);
    const uint32_t mbar = sb + OFF_MBAR;

    const int tid  = threadIdx.x;
    const int wid  = tid >> 5;
    const int lane = tid & 31;
    const int q    = lane & 3;
    const int r4   = lane >> 2;
    const int ng   = (int)(blockIdx.x & (NGROUPS - 1));
    const int e0   = ng * BN;

    if (tid == 0) MBARRIER_INIT(mbar, THREADS);

    // ---- load B tile (WeffT rows e0..e0+63), permuted within slices ----
    for (int u = tid; u < 2048; u += THREADS) {
        int r  = u >> 5;          // Bs row 0..63
        int ch = u & 31;          // 16B chunk along k
        int esrc = e0 + (r & ~15) + permcol(r & 15);
        uint4 v = *reinterpret_cast<const uint4*>(&g_weffT[esrc * W_SZ + ch * 8]);
        *reinterpret_cast<uint4*>(Bs + r * PB + ch * 8) = v;
    }

    // ---- per-thread bias: 4 contiguous cols ----
    const int colb = e0 + wid * 16 + 4 * q;
    const float4 bias4 = *reinterpret_cast<const float4*>(bias + colb);

    // ---- ldmatrix base address for this warp's 16-row B slice ----
    const uint32_t sbB = smem_to_u32(Bs);
    const int brow = wid * 16 + (lane & 7) + ((lane & 16) ? 8 : 0);
    const int bkof = (lane & 8) ? 8 : 0;
    const uint32_t baddr0 = sbB + (uint32_t)(brow * PB + bkof) * 2u;

    // ---- initial segment load for first M-tile (383 floats, 128 thr) ----
    const int mt0 = (int)(blockIdx.x >> 3);
    {
        int bidx = mt0 >> 6, t0 = (mt0 & 63) * BM;
        const float* xb = x + bidx * T_SZ;
        #pragma unroll
        for (int c = 0; c < 3; c++) {
            int j = tid + c * 128;
            int gx = t0 + j - (W_SZ - 1);
            if (j < 383) seg[0][j] = (gx >= 0) ? xb[gx] : 0.0f;
        }
    }
    __syncthreads();   // B tile + seg[0] + mbarrier init visible

    int pb = 0, ph = 0;
    for (int mt = mt0; mt < MTILES; mt += CTAS_PER_N, pb ^= 1) {
        // ---- prefetch next segment into registers (all loads guarded) ----
        const int mtn = mt + CTAS_PER_N;
        float p0 = 0.0f, p1 = 0.0f, p2 = 0.0f;
        if (mtn < MTILES) {
            int bidx = mtn >> 6, t0 = (mtn & 63) * BM;
            const float* xb = x + bidx * T_SZ;
            int g0 = t0 + tid - (W_SZ - 1);   // j = tid        in [0,128)
            int g1 = g0 + 128;                // j = tid + 128  in [128,256)
            int g2 = g0 + 256;                // j = tid + 256  in [256,384)
            if (g0 >= 0) p0 = xb[g0];
            if (g1 >= 0) p1 = xb[g1];
            if (tid < 127 && g2 >= 0) p2 = xb[g2];
        }

        // ---- MMA mainloop: K=256 (16 k-steps), 8 m-tiles, 2 n-tiles ----
        float acc[8][2][4];
        #pragma unroll
        for (int m = 0; m < 8; m++)
            #pragma unroll
            for (int n = 0; n < 2; n++)
                #pragma unroll
                for (int c = 0; c < 4; c++) acc[m][n][c] = 0.0f;

        const float* sg = seg[pb];
        const int base0 = r4 + 2 * q;

        // Toeplitz A: av[j] = half2(seg[base0 + 16*ks + 8j .. +1])
        uint32_t av[17];
        #pragma unroll
        for (int j = 0; j < 17; j++) av[j] = ldcvt(sg + base0 + 8 * j);

        #pragma unroll
        for (int ks = 0; ks < 16; ks++) {
            uint32_t b0, b1, b2, b3;
            ldmatrix_x4(b0, b1, b2, b3, baddr0 + (uint32_t)(ks * 32));
            #pragma unroll
            for (int m = 0; m < 8; m++) {
                mma16816(acc[m][0], av[2*m], av[2*m+1], av[2*m+1], av[2*m+2], b0, b1);
                mma16816(acc[m][1], av[2*m], av[2*m+1], av[2*m+1], av[2*m+2], b2, b3);
            }
            if (ks < 15) {
                #pragma unroll
                for (int j = 0; j < 15; j++) av[j] = av[j + 2];
                av[15] = ldcvt(sg + base0 + 16 * (ks + 1) + 120);
                av[16] = ldcvt(sg + base0 + 16 * (ks + 1) + 128);
            }
        }

        // ---- store prefetched segment, then ARRIVE (mainloop reads done) ----
        if (mtn < MTILES) {
            seg[pb ^ 1][tid] = p0;
            seg[pb ^ 1][tid + 128] = p1;
            if (tid < 127) seg[pb ^ 1][tid + 256] = p2;
            MBARRIER_ARRIVE(mbar);
        }

        // ---- epilogue (outside critical path): bias + STG.128 ----
        const size_t rowb = (size_t)mt * BM + (size_t)r4;
        #pragma unroll
        for (int m = 0; m < 8; m++) {
            float* o0 = out + (rowb + 16 * m) * EMB + colb;
            float* o1 = o0 + 8 * EMB;
            float4 v0 = make_float4(acc[m][0][0] + bias4.x, acc[m][0][1] + bias4.y,
                                    acc[m][1][0] + bias4.z, acc[m][1][1] + bias4.w);
            float4 v1 = make_float4(acc[m][0][2] + bias4.x, acc[m][0][3] + bias4.y,
                                    acc[m][1][2] + bias4.z, acc[m][1][3] + bias4.w);
            *reinterpret_cast<float4*>(o0) = v0;
            *reinterpret_cast<float4*>(o1) = v1;
        }

        // ---- wait for all warps' arrivals before next mainloop ----
        if (mtn < MTILES) {
            MBARRIER_WAIT_PARITY(mbar, ph);
            ph ^= 1;
        }
    }
}

// ============================================================
extern "C" void kernel_launch(void* const* d_in, const int* in_sizes, int n_in,
                              void* d_out, int out_size) {
    const float* x  = nullptr;
    const float* wt = nullptr;
    const float* bs = nullptr;
    for (int i = 0; i < n_in; i++) {
        if (in_sizes[i] == B_SZ * T_SZ)        x  = (const float*)d_in[i];
        else if (in_sizes[i] == EMB * NFEAT)   wt = (const float*)d_in[i];
        else if (in_sizes[i] == EMB)           bs = (const float*)d_in[i];
    }

    weff_kernel<<<EMB, 256>>>(wt);

    cudaFuncSetAttribute(fft_gemm_kernel,
                         cudaFuncAttributeMaxDynamicSharedMemorySize, SMEM_TOTAL);
    fft_gemm_kernel<<<GRID, THREADS, SMEM_TOTAL>>>(x, bs, (float*)d_out);
}